// round 5
// baseline (speedup 1.0000x reference)
#include <cuda_runtime.h>

#define NN   20000
#define INCH 256
#define HEADS 8
#define HID  32
#define C1   256      // HEADS*HID
#define OUTC 40
#define E0   320000
#define ET   340000   // + self loops
#define NEG  0.2f

// ---------------- scratch (device globals; no allocation allowed) ----------
__device__ float g_h1[NN * C1];        // x @ W1
__device__ float g_as1[NN * HEADS];
__device__ float g_ad1[NN * HEADS];
__device__ float g_e1[ET * HEADS];     // exp(edge logits), CSR order
__device__ float g_out1[NN * C1];      // elu(aggr + b1)
__device__ float g_h2[NN * OUTC];      // out1 @ W2
__device__ float g_as2[NN];
__device__ float g_ad2[NN];
__device__ float g_e2[ET];             // CSR order
__device__ int   g_deg[NN];
__device__ int   g_off[NN + 1];
__device__ int   g_cur[NN];
__device__ int   g_src[ET];            // CSR payload: src node per slot

// ---------------- helpers ---------------------------------------------------
__device__ __forceinline__ unsigned f2tf32(float f) {
    unsigned r;
    asm volatile("cvt.rna.tf32.f32 %0, %1;" : "=r"(r) : "f"(f));
    return r;
}
__device__ __forceinline__ void mma_tf32(float* c, const unsigned* a, unsigned b0, unsigned b1) {
    asm volatile(
        "mma.sync.aligned.m16n8k8.row.col.f32.tf32.tf32.f32 "
        "{%0,%1,%2,%3}, {%4,%5,%6,%7}, {%8,%9}, {%0,%1,%2,%3};"
        : "+f"(c[0]), "+f"(c[1]), "+f"(c[2]), "+f"(c[3])
        : "r"(a[0]), "r"(a[1]), "r"(a[2]), "r"(a[3]), "r"(b0), "r"(b1));
}

// ---------------- CSR build --------------------------------------------------
__global__ void zero_deg() {
    int i = blockIdx.x * blockDim.x + threadIdx.x;
    if (i < NN) g_deg[i] = 0;
}

__global__ void deg_hist(const int* __restrict__ ei) {
    int e = blockIdx.x * blockDim.x + threadIdx.x;
    if (e >= ET) return;
    int d = (e < E0) ? ei[E0 + e] : (e - E0);
    atomicAdd(&g_deg[d], 1);
}

// single-block exclusive scan over g_deg -> g_off, g_cur
__global__ __launch_bounds__(1024) void scan_kernel() {
    __shared__ int wsum[32];
    __shared__ int carry_s;
    int tid = threadIdx.x;
    int lane = tid & 31, wid = tid >> 5;
    if (tid == 0) carry_s = 0;
    __syncthreads();
    for (int base = 0; base < NN; base += 1024) {
        int idx = base + tid;
        int v = (idx < NN) ? g_deg[idx] : 0;
        int x = v;
#pragma unroll
        for (int o = 1; o < 32; o <<= 1) {
            int y = __shfl_up_sync(~0u, x, o);
            if (lane >= o) x += y;
        }
        if (lane == 31) wsum[wid] = x;
        __syncthreads();
        if (wid == 0) {
            int w = wsum[lane];
#pragma unroll
            for (int o = 1; o < 32; o <<= 1) {
                int y = __shfl_up_sync(~0u, w, o);
                if (lane >= o) w += y;
            }
            wsum[lane] = w;
        }
        __syncthreads();
        int incl = x + (wid ? wsum[wid - 1] : 0);
        int excl = carry_s + incl - v;
        if (idx < NN) { g_off[idx] = excl; g_cur[idx] = excl; }
        __syncthreads();
        if (tid == 0) carry_s += wsum[31];
        __syncthreads();
    }
    if (tid == 0) g_off[NN] = carry_s;
}

__global__ void fill_csr(const int* __restrict__ ei) {
    int e = blockIdx.x * blockDim.x + threadIdx.x;
    if (e >= ET) return;
    int s, d;
    if (e < E0) { s = ei[e]; d = ei[E0 + e]; } else { s = d = e - E0; }
    int pos = atomicAdd(&g_cur[d], 1);
    g_src[pos] = s;
}

// ---------------- GEMM1: h1 = x @ W1  (tf32 tensor cores) -------------------
__global__ __launch_bounds__(256) void gemm1_kernel(const float* __restrict__ x,
                                                    const float* __restrict__ W1) {
    __shared__ float As[128][36];
    __shared__ float Bs[32][136];
    int tid = threadIdx.x;
    int lane = tid & 31, wid = tid >> 5;
    int wm = wid & 3, wn = wid >> 2;
    int g = lane >> 2, tg = lane & 3;
    int m0 = blockIdx.y * 128, n0 = blockIdx.x * 128;

    float acc[2][8][4];
#pragma unroll
    for (int i = 0; i < 2; i++)
#pragma unroll
        for (int j = 0; j < 8; j++)
#pragma unroll
            for (int k = 0; k < 4; k++) acc[i][j][k] = 0.f;

    int a_r = tid >> 3;
    int a_c = (tid & 7) * 4;
    int b_r = tid >> 3;
    int b_c0 = tid & 7;

    for (int k0 = 0; k0 < INCH; k0 += 32) {
#pragma unroll
        for (int j = 0; j < 4; j++) {
            int r = a_r + 32 * j;
            int gm = m0 + r;
            float4 v = make_float4(0.f, 0.f, 0.f, 0.f);
            if (gm < NN) v = *reinterpret_cast<const float4*>(&x[(size_t)gm * INCH + k0 + a_c]);
            As[r][a_c + 0] = __uint_as_float(f2tf32(v.x));
            As[r][a_c + 1] = __uint_as_float(f2tf32(v.y));
            As[r][a_c + 2] = __uint_as_float(f2tf32(v.z));
            As[r][a_c + 3] = __uint_as_float(f2tf32(v.w));
        }
#pragma unroll
        for (int j = 0; j < 4; j++) {
            int c = (b_c0 + 8 * j) * 4;
            float4 v = *reinterpret_cast<const float4*>(&W1[(size_t)(k0 + b_r) * C1 + n0 + c]);
            Bs[b_r][c + 0] = __uint_as_float(f2tf32(v.x));
            Bs[b_r][c + 1] = __uint_as_float(f2tf32(v.y));
            Bs[b_r][c + 2] = __uint_as_float(f2tf32(v.z));
            Bs[b_r][c + 3] = __uint_as_float(f2tf32(v.w));
        }
        __syncthreads();
#pragma unroll
        for (int ks = 0; ks < 4; ks++) {
            int kk = ks * 8;
            unsigned a[2][4];
#pragma unroll
            for (int mi = 0; mi < 2; mi++) {
                int rb = wm * 32 + mi * 16 + g;
                a[mi][0] = __float_as_uint(As[rb][kk + tg]);
                a[mi][1] = __float_as_uint(As[rb + 8][kk + tg]);
                a[mi][2] = __float_as_uint(As[rb][kk + tg + 4]);
                a[mi][3] = __float_as_uint(As[rb + 8][kk + tg + 4]);
            }
#pragma unroll
            for (int nt = 0; nt < 8; nt++) {
                int col = wn * 64 + nt * 8 + g;
                unsigned b0 = __float_as_uint(Bs[kk + tg][col]);
                unsigned b1 = __float_as_uint(Bs[kk + tg + 4][col]);
                mma_tf32(acc[0][nt], a[0], b0, b1);
                mma_tf32(acc[1][nt], a[1], b0, b1);
            }
        }
        __syncthreads();
    }
#pragma unroll
    for (int mi = 0; mi < 2; mi++) {
        int r = m0 + wm * 32 + mi * 16 + g;
#pragma unroll
        for (int nt = 0; nt < 8; nt++) {
            int c = n0 + wn * 64 + nt * 8 + tg * 2;
            if (r < NN) {
                g_h1[(size_t)r * C1 + c]     = acc[mi][nt][0];
                g_h1[(size_t)r * C1 + c + 1] = acc[mi][nt][1];
            }
            if (r + 8 < NN) {
                g_h1[(size_t)(r + 8) * C1 + c]     = acc[mi][nt][2];
                g_h1[(size_t)(r + 8) * C1 + c + 1] = acc[mi][nt][3];
            }
        }
    }
}

// ---------------- alpha projections (layer 1) --------------------------------
__global__ void alpha1_kernel(const float* __restrict__ a_src, const float* __restrict__ a_dst) {
    int n = blockIdx.x;
    int t = threadIdx.x;
    int h = t >> 5, l = t & 31;
    float v = g_h1[n * C1 + t];
    float s = v * a_src[t];
    float d = v * a_dst[t];
#pragma unroll
    for (int o = 16; o; o >>= 1) {
        s += __shfl_xor_sync(~0u, s, o);
        d += __shfl_xor_sync(~0u, d, o);
    }
    if (l == 0) { g_as1[n * HEADS + h] = s; g_ad1[n * HEADS + h] = d; }
}

// ---------------- layer1 gather: exp + den + aggregate + bias + ELU ---------
__global__ __launch_bounds__(256) void gather1(const float* __restrict__ b1) {
    int d = blockIdx.x;
    int tid = threadIdx.x;
    int start = g_off[d];
    int deg = g_off[d + 1] - start;

    __shared__ float sden[HEADS];
    __shared__ float sad[HEADS];
    if (tid < HEADS) { sden[tid] = 0.f; sad[tid] = g_ad1[d * HEADS + tid]; }
    __syncthreads();

    // pass1: exp per (edge, head) -> g_e1 (CSR order), smem denominators
    for (int idx = tid; idx < deg * HEADS; idx += 256) {
        int i = idx >> 3, h = idx & 7;
        int s = g_src[start + i];
        float v = g_as1[s * HEADS + h] + sad[h];
        v = v > 0.f ? v : NEG * v;
        float ex = __expf(v);
        g_e1[(size_t)(start + i) * HEADS + h] = ex;
        atomicAdd(&sden[h], ex);
    }
    __syncthreads();

    // pass2: per-channel register accumulation (divide by den once at end)
    int ch = tid;
    int h = ch >> 5;
    float acc = 0.f;
    for (int i = 0; i < deg; i++) {
        int s = g_src[start + i];                                // broadcast
        float ex = g_e1[(size_t)(start + i) * HEADS + h];        // broadcast
        acc += ex * g_h1[(size_t)s * C1 + ch];
    }
    float o = acc / (sden[h] + 1e-16f) + b1[ch];
    g_out1[(size_t)d * C1 + ch] = o > 0.f ? o : expm1f(o);
}

// ---------------- GEMM2: h2 = out1 @ W2, + fused alpha2 ---------------------
__global__ __launch_bounds__(256) void gemm2_kernel(const float* __restrict__ W2,
                                                    const float* __restrict__ a2s,
                                                    const float* __restrict__ a2d) {
    __shared__ float As[128][36];
    __shared__ float Bs[32][44];
    int tid = threadIdx.x;
    int lane = tid & 31, wid = tid >> 5;
    int g = lane >> 2, tg = lane & 3;
    int m0 = blockIdx.x * 128;

    float acc[5][4];
#pragma unroll
    for (int j = 0; j < 5; j++)
#pragma unroll
        for (int k = 0; k < 4; k++) acc[j][k] = 0.f;

    int a_r = tid >> 3;
    int a_c = (tid & 7) * 4;

    for (int k0 = 0; k0 < C1; k0 += 32) {
#pragma unroll
        for (int j = 0; j < 4; j++) {
            int r = a_r + 32 * j;
            int gm = m0 + r;
            float4 v = make_float4(0.f, 0.f, 0.f, 0.f);
            if (gm < NN) v = *reinterpret_cast<const float4*>(&g_out1[(size_t)gm * C1 + k0 + a_c]);
            As[r][a_c + 0] = __uint_as_float(f2tf32(v.x));
            As[r][a_c + 1] = __uint_as_float(f2tf32(v.y));
            As[r][a_c + 2] = __uint_as_float(f2tf32(v.z));
            As[r][a_c + 3] = __uint_as_float(f2tf32(v.w));
        }
        for (int idx = tid; idx < 32 * OUTC; idx += 256) {
            int r = idx / OUTC, c = idx % OUTC;
            Bs[r][c] = __uint_as_float(f2tf32(W2[(size_t)(k0 + r) * OUTC + c]));
        }
        __syncthreads();
#pragma unroll
        for (int ks = 0; ks < 4; ks++) {
            int kk = ks * 8;
            unsigned a[4];
            int rb = wid * 16 + g;
            a[0] = __float_as_uint(As[rb][kk + tg]);
            a[1] = __float_as_uint(As[rb + 8][kk + tg]);
            a[2] = __float_as_uint(As[rb][kk + tg + 4]);
            a[3] = __float_as_uint(As[rb + 8][kk + tg + 4]);
#pragma unroll
            for (int nt = 0; nt < 5; nt++) {
                int col = nt * 8 + g;
                unsigned b0 = __float_as_uint(Bs[kk + tg][col]);
                unsigned b1r = __float_as_uint(Bs[kk + tg + 4][col]);
                mma_tf32(acc[nt], a, b0, b1r);
            }
        }
        __syncthreads();
    }
    int rlo = m0 + wid * 16 + g;
    int rhi = rlo + 8;
    float s_lo = 0.f, s_hi = 0.f, d_lo = 0.f, d_hi = 0.f;
#pragma unroll
    for (int nt = 0; nt < 5; nt++) {
        int c = nt * 8 + tg * 2;
        float w0s = a2s[c], w1s = a2s[c + 1];
        float w0d = a2d[c], w1d = a2d[c + 1];
        if (rlo < NN) {
            g_h2[(size_t)rlo * OUTC + c]     = acc[nt][0];
            g_h2[(size_t)rlo * OUTC + c + 1] = acc[nt][1];
        }
        if (rhi < NN) {
            g_h2[(size_t)rhi * OUTC + c]     = acc[nt][2];
            g_h2[(size_t)rhi * OUTC + c + 1] = acc[nt][3];
        }
        s_lo += acc[nt][0] * w0s + acc[nt][1] * w1s;
        s_hi += acc[nt][2] * w0s + acc[nt][3] * w1s;
        d_lo += acc[nt][0] * w0d + acc[nt][1] * w1d;
        d_hi += acc[nt][2] * w0d + acc[nt][3] * w1d;
    }
#pragma unroll
    for (int o = 1; o <= 2; o <<= 1) {
        s_lo += __shfl_xor_sync(~0u, s_lo, o);
        s_hi += __shfl_xor_sync(~0u, s_hi, o);
        d_lo += __shfl_xor_sync(~0u, d_lo, o);
        d_hi += __shfl_xor_sync(~0u, d_hi, o);
    }
    if (tg == 0) {
        if (rlo < NN) { g_as2[rlo] = s_lo; g_ad2[rlo] = d_lo; }
        if (rhi < NN) { g_as2[rhi] = s_hi; g_ad2[rhi] = d_hi; }
    }
}

// ---------------- layer2 gather: exp + den + aggregate + bias + log_softmax --
__global__ __launch_bounds__(64) void gather2(const float* __restrict__ b2,
                                              float* __restrict__ out) {
    int d = blockIdx.x;
    int tid = threadIdx.x;
    int start = g_off[d];
    int deg = g_off[d + 1] - start;

    __shared__ float sden;
    __shared__ float svals[OUTC];
    if (tid == 0) sden = 0.f;
    __syncthreads();

    float add = g_ad2[d];
    float part = 0.f;
    for (int i = tid; i < deg; i += 64) {
        int s = g_src[start + i];
        float v = g_as2[s] + add;
        v = v > 0.f ? v : NEG * v;
        float ex = __expf(v);
        g_e2[start + i] = ex;
        part += ex;
    }
    atomicAdd(&sden, part);
    __syncthreads();

    if (tid < OUTC) {
        float acc = 0.f;
        for (int i = 0; i < deg; i++) {
            int s = g_src[start + i];
            acc += g_e2[start + i] * g_h2[(size_t)s * OUTC + tid];
        }
        svals[tid] = acc / (sden + 1e-16f) + b2[tid];
    }
    __syncthreads();
    if (tid < OUTC) {
        float m = -1e30f;
#pragma unroll 8
        for (int j = 0; j < OUTC; j++) m = fmaxf(m, svals[j]);
        float sum = 0.f;
#pragma unroll 8
        for (int j = 0; j < OUTC; j++) sum += __expf(svals[j] - m);
        out[(size_t)d * OUTC + tid] = svals[tid] - m - logf(sum);
    }
}

// ---------------- launch --------------------------------------------------------
extern "C" void kernel_launch(void* const* d_in, const int* in_sizes, int n_in,
                              void* d_out, int out_size) {
    const float* x   = (const float*)d_in[0];
    const int*   ei  = (const int*)d_in[1];
    const float* W1  = (const float*)d_in[2];
    const float* a1s = (const float*)d_in[3];
    const float* a1d = (const float*)d_in[4];
    const float* b1  = (const float*)d_in[5];
    const float* W2  = (const float*)d_in[6];
    const float* a2s = (const float*)d_in[7];
    const float* a2d = (const float*)d_in[8];
    const float* b2  = (const float*)d_in[9];
    float*       out = (float*)d_out;

    // CSR build
    zero_deg<<<(NN + 255) / 256, 256>>>();
    deg_hist<<<(ET + 255) / 256, 256>>>(ei);
    scan_kernel<<<1, 1024>>>();
    fill_csr<<<(ET + 255) / 256, 256>>>(ei);

    gemm1_kernel<<<dim3(2, (NN + 127) / 128), 256>>>(x, W1);
    alpha1_kernel<<<NN, 256>>>(a1s, a1d);

    gather1<<<NN, 256>>>(b1);

    gemm2_kernel<<<(NN + 127) / 128, 256>>>(W2, a2s, a2d);

    gather2<<<NN, 64>>>(b2, out);
}

// round 6
// speedup vs baseline: 1.0001x; 1.0001x over previous
#include <cuda_runtime.h>

#define NN   20000
#define INCH 256
#define HEADS 8
#define HID  32
#define C1   256      // HEADS*HID
#define OUTC 40
#define E0   320000
#define ET   340000   // + self loops
#define NEG  0.2f

// ---------------- scratch (device globals; no allocation allowed) ----------
__device__ float g_h1[NN * C1];        // x @ W1
__device__ float g_as1[NN * HEADS];
__device__ float g_ad1[NN * HEADS];
__device__ float g_e1[ET * HEADS];     // exp(edge logits), CSR order
__device__ float g_out1[NN * C1];      // elu(aggr + b1)
__device__ float g_h2[NN * OUTC];      // out1 @ W2
__device__ float g_as2[NN];
__device__ float g_ad2[NN];
__device__ float g_e2[ET];             // CSR order
__device__ int   g_deg[NN];
__device__ int   g_off[NN + 1];
__device__ int   g_cur[NN];
__device__ int   g_src[ET];            // CSR payload: src node per slot

// ---------------- helpers ---------------------------------------------------
__device__ __forceinline__ unsigned f2tf32(float f) {
    unsigned r;
    asm volatile("cvt.rna.tf32.f32 %0, %1;" : "=r"(r) : "f"(f));
    return r;
}
__device__ __forceinline__ void mma_tf32(float* c, const unsigned* a, unsigned b0, unsigned b1) {
    asm volatile(
        "mma.sync.aligned.m16n8k8.row.col.f32.tf32.tf32.f32 "
        "{%0,%1,%2,%3}, {%4,%5,%6,%7}, {%8,%9}, {%0,%1,%2,%3};"
        : "+f"(c[0]), "+f"(c[1]), "+f"(c[2]), "+f"(c[3])
        : "r"(a[0]), "r"(a[1]), "r"(a[2]), "r"(a[3]), "r"(b0), "r"(b1));
}

// ---------------- CSR build --------------------------------------------------
__global__ void zero_deg() {
    int i = blockIdx.x * blockDim.x + threadIdx.x;
    if (i < NN) g_deg[i] = 0;
}

__global__ void deg_hist(const int* __restrict__ ei) {
    int e = blockIdx.x * blockDim.x + threadIdx.x;
    if (e >= ET) return;
    int d = (e < E0) ? ei[E0 + e] : (e - E0);
    atomicAdd(&g_deg[d], 1);
}

// single-block exclusive scan over g_deg -> g_off, g_cur
__global__ __launch_bounds__(1024) void scan_kernel() {
    __shared__ int wsum[32];
    __shared__ int carry_s;
    int tid = threadIdx.x;
    int lane = tid & 31, wid = tid >> 5;
    if (tid == 0) carry_s = 0;
    __syncthreads();
    for (int base = 0; base < NN; base += 1024) {
        int idx = base + tid;
        int v = (idx < NN) ? g_deg[idx] : 0;
        int x = v;
#pragma unroll
        for (int o = 1; o < 32; o <<= 1) {
            int y = __shfl_up_sync(~0u, x, o);
            if (lane >= o) x += y;
        }
        if (lane == 31) wsum[wid] = x;
        __syncthreads();
        if (wid == 0) {
            int w = wsum[lane];
#pragma unroll
            for (int o = 1; o < 32; o <<= 1) {
                int y = __shfl_up_sync(~0u, w, o);
                if (lane >= o) w += y;
            }
            wsum[lane] = w;
        }
        __syncthreads();
        int incl = x + (wid ? wsum[wid - 1] : 0);
        int excl = carry_s + incl - v;
        if (idx < NN) { g_off[idx] = excl; g_cur[idx] = excl; }
        __syncthreads();
        if (tid == 0) carry_s += wsum[31];
        __syncthreads();
    }
    if (tid == 0) g_off[NN] = carry_s;
}

__global__ void fill_csr(const int* __restrict__ ei) {
    int e = blockIdx.x * blockDim.x + threadIdx.x;
    if (e >= ET) return;
    int s, d;
    if (e < E0) { s = ei[e]; d = ei[E0 + e]; } else { s = d = e - E0; }
    int pos = atomicAdd(&g_cur[d], 1);
    g_src[pos] = s;
}

// ---------------- GEMM1: h1 = x @ W1  (tf32 tensor cores) -------------------
__global__ __launch_bounds__(256) void gemm1_kernel(const float* __restrict__ x,
                                                    const float* __restrict__ W1) {
    __shared__ float As[128][36];
    __shared__ float Bs[32][136];
    int tid = threadIdx.x;
    int lane = tid & 31, wid = tid >> 5;
    int wm = wid & 3, wn = wid >> 2;
    int g = lane >> 2, tg = lane & 3;
    int m0 = blockIdx.y * 128, n0 = blockIdx.x * 128;

    float acc[2][8][4];
#pragma unroll
    for (int i = 0; i < 2; i++)
#pragma unroll
        for (int j = 0; j < 8; j++)
#pragma unroll
            for (int k = 0; k < 4; k++) acc[i][j][k] = 0.f;

    int a_r = tid >> 3;
    int a_c = (tid & 7) * 4;
    int b_r = tid >> 3;
    int b_c0 = tid & 7;

    for (int k0 = 0; k0 < INCH; k0 += 32) {
#pragma unroll
        for (int j = 0; j < 4; j++) {
            int r = a_r + 32 * j;
            int gm = m0 + r;
            float4 v = make_float4(0.f, 0.f, 0.f, 0.f);
            if (gm < NN) v = *reinterpret_cast<const float4*>(&x[(size_t)gm * INCH + k0 + a_c]);
            As[r][a_c + 0] = __uint_as_float(f2tf32(v.x));
            As[r][a_c + 1] = __uint_as_float(f2tf32(v.y));
            As[r][a_c + 2] = __uint_as_float(f2tf32(v.z));
            As[r][a_c + 3] = __uint_as_float(f2tf32(v.w));
        }
#pragma unroll
        for (int j = 0; j < 4; j++) {
            int c = (b_c0 + 8 * j) * 4;
            float4 v = *reinterpret_cast<const float4*>(&W1[(size_t)(k0 + b_r) * C1 + n0 + c]);
            Bs[b_r][c + 0] = __uint_as_float(f2tf32(v.x));
            Bs[b_r][c + 1] = __uint_as_float(f2tf32(v.y));
            Bs[b_r][c + 2] = __uint_as_float(f2tf32(v.z));
            Bs[b_r][c + 3] = __uint_as_float(f2tf32(v.w));
        }
        __syncthreads();
#pragma unroll
        for (int ks = 0; ks < 4; ks++) {
            int kk = ks * 8;
            unsigned a[2][4];
#pragma unroll
            for (int mi = 0; mi < 2; mi++) {
                int rb = wm * 32 + mi * 16 + g;
                a[mi][0] = __float_as_uint(As[rb][kk + tg]);
                a[mi][1] = __float_as_uint(As[rb + 8][kk + tg]);
                a[mi][2] = __float_as_uint(As[rb][kk + tg + 4]);
                a[mi][3] = __float_as_uint(As[rb + 8][kk + tg + 4]);
            }
#pragma unroll
            for (int nt = 0; nt < 8; nt++) {
                int col = wn * 64 + nt * 8 + g;
                unsigned b0 = __float_as_uint(Bs[kk + tg][col]);
                unsigned b1 = __float_as_uint(Bs[kk + tg + 4][col]);
                mma_tf32(acc[0][nt], a[0], b0, b1);
                mma_tf32(acc[1][nt], a[1], b0, b1);
            }
        }
        __syncthreads();
    }
#pragma unroll
    for (int mi = 0; mi < 2; mi++) {
        int r = m0 + wm * 32 + mi * 16 + g;
#pragma unroll
        for (int nt = 0; nt < 8; nt++) {
            int c = n0 + wn * 64 + nt * 8 + tg * 2;
            if (r < NN) {
                g_h1[(size_t)r * C1 + c]     = acc[mi][nt][0];
                g_h1[(size_t)r * C1 + c + 1] = acc[mi][nt][1];
            }
            if (r + 8 < NN) {
                g_h1[(size_t)(r + 8) * C1 + c]     = acc[mi][nt][2];
                g_h1[(size_t)(r + 8) * C1 + c + 1] = acc[mi][nt][3];
            }
        }
    }
}

// ---------------- alpha projections (layer 1) --------------------------------
__global__ void alpha1_kernel(const float* __restrict__ a_src, const float* __restrict__ a_dst) {
    int n = blockIdx.x;
    int t = threadIdx.x;
    int h = t >> 5, l = t & 31;
    float v = g_h1[n * C1 + t];
    float s = v * a_src[t];
    float d = v * a_dst[t];
#pragma unroll
    for (int o = 16; o; o >>= 1) {
        s += __shfl_xor_sync(~0u, s, o);
        d += __shfl_xor_sync(~0u, d, o);
    }
    if (l == 0) { g_as1[n * HEADS + h] = s; g_ad1[n * HEADS + h] = d; }
}

// ---------------- layer1 gather: exp + den + aggregate + bias + ELU ---------
__global__ __launch_bounds__(256) void gather1(const float* __restrict__ b1) {
    int d = blockIdx.x;
    int tid = threadIdx.x;
    int start = g_off[d];
    int deg = g_off[d + 1] - start;

    __shared__ float sden[HEADS];
    __shared__ float sad[HEADS];
    if (tid < HEADS) { sden[tid] = 0.f; sad[tid] = g_ad1[d * HEADS + tid]; }
    __syncthreads();

    // pass1: exp per (edge, head) -> g_e1 (CSR order), smem denominators
    for (int idx = tid; idx < deg * HEADS; idx += 256) {
        int i = idx >> 3, h = idx & 7;
        int s = g_src[start + i];
        float v = g_as1[s * HEADS + h] + sad[h];
        v = v > 0.f ? v : NEG * v;
        float ex = __expf(v);
        g_e1[(size_t)(start + i) * HEADS + h] = ex;
        atomicAdd(&sden[h], ex);
    }
    __syncthreads();

    // pass2: per-channel register accumulation (divide by den once at end)
    int ch = tid;
    int h = ch >> 5;
    float acc = 0.f;
    for (int i = 0; i < deg; i++) {
        int s = g_src[start + i];                                // broadcast
        float ex = g_e1[(size_t)(start + i) * HEADS + h];        // broadcast
        acc += ex * g_h1[(size_t)s * C1 + ch];
    }
    float o = acc / (sden[h] + 1e-16f) + b1[ch];
    g_out1[(size_t)d * C1 + ch] = o > 0.f ? o : expm1f(o);
}

// ---------------- GEMM2: h2 = out1 @ W2, + fused alpha2 ---------------------
__global__ __launch_bounds__(256) void gemm2_kernel(const float* __restrict__ W2,
                                                    const float* __restrict__ a2s,
                                                    const float* __restrict__ a2d) {
    __shared__ float As[128][36];
    __shared__ float Bs[32][44];
    int tid = threadIdx.x;
    int lane = tid & 31, wid = tid >> 5;
    int g = lane >> 2, tg = lane & 3;
    int m0 = blockIdx.x * 128;

    float acc[5][4];
#pragma unroll
    for (int j = 0; j < 5; j++)
#pragma unroll
        for (int k = 0; k < 4; k++) acc[j][k] = 0.f;

    int a_r = tid >> 3;
    int a_c = (tid & 7) * 4;

    for (int k0 = 0; k0 < C1; k0 += 32) {
#pragma unroll
        for (int j = 0; j < 4; j++) {
            int r = a_r + 32 * j;
            int gm = m0 + r;
            float4 v = make_float4(0.f, 0.f, 0.f, 0.f);
            if (gm < NN) v = *reinterpret_cast<const float4*>(&g_out1[(size_t)gm * C1 + k0 + a_c]);
            As[r][a_c + 0] = __uint_as_float(f2tf32(v.x));
            As[r][a_c + 1] = __uint_as_float(f2tf32(v.y));
            As[r][a_c + 2] = __uint_as_float(f2tf32(v.z));
            As[r][a_c + 3] = __uint_as_float(f2tf32(v.w));
        }
        for (int idx = tid; idx < 32 * OUTC; idx += 256) {
            int r = idx / OUTC, c = idx % OUTC;
            Bs[r][c] = __uint_as_float(f2tf32(W2[(size_t)(k0 + r) * OUTC + c]));
        }
        __syncthreads();
#pragma unroll
        for (int ks = 0; ks < 4; ks++) {
            int kk = ks * 8;
            unsigned a[4];
            int rb = wid * 16 + g;
            a[0] = __float_as_uint(As[rb][kk + tg]);
            a[1] = __float_as_uint(As[rb + 8][kk + tg]);
            a[2] = __float_as_uint(As[rb][kk + tg + 4]);
            a[3] = __float_as_uint(As[rb + 8][kk + tg + 4]);
#pragma unroll
            for (int nt = 0; nt < 5; nt++) {
                int col = nt * 8 + g;
                unsigned b0 = __float_as_uint(Bs[kk + tg][col]);
                unsigned b1r = __float_as_uint(Bs[kk + tg + 4][col]);
                mma_tf32(acc[nt], a, b0, b1r);
            }
        }
        __syncthreads();
    }
    int rlo = m0 + wid * 16 + g;
    int rhi = rlo + 8;
    float s_lo = 0.f, s_hi = 0.f, d_lo = 0.f, d_hi = 0.f;
#pragma unroll
    for (int nt = 0; nt < 5; nt++) {
        int c = nt * 8 + tg * 2;
        float w0s = a2s[c], w1s = a2s[c + 1];
        float w0d = a2d[c], w1d = a2d[c + 1];
        if (rlo < NN) {
            g_h2[(size_t)rlo * OUTC + c]     = acc[nt][0];
            g_h2[(size_t)rlo * OUTC + c + 1] = acc[nt][1];
        }
        if (rhi < NN) {
            g_h2[(size_t)rhi * OUTC + c]     = acc[nt][2];
            g_h2[(size_t)rhi * OUTC + c + 1] = acc[nt][3];
        }
        s_lo += acc[nt][0] * w0s + acc[nt][1] * w1s;
        s_hi += acc[nt][2] * w0s + acc[nt][3] * w1s;
        d_lo += acc[nt][0] * w0d + acc[nt][1] * w1d;
        d_hi += acc[nt][2] * w0d + acc[nt][3] * w1d;
    }
#pragma unroll
    for (int o = 1; o <= 2; o <<= 1) {
        s_lo += __shfl_xor_sync(~0u, s_lo, o);
        s_hi += __shfl_xor_sync(~0u, s_hi, o);
        d_lo += __shfl_xor_sync(~0u, d_lo, o);
        d_hi += __shfl_xor_sync(~0u, d_hi, o);
    }
    if (tg == 0) {
        if (rlo < NN) { g_as2[rlo] = s_lo; g_ad2[rlo] = d_lo; }
        if (rhi < NN) { g_as2[rhi] = s_hi; g_ad2[rhi] = d_hi; }
    }
}

// ---------------- layer2 gather: exp + den + aggregate + bias + log_softmax --
__global__ __launch_bounds__(64) void gather2(const float* __restrict__ b2,
                                              float* __restrict__ out) {
    int d = blockIdx.x;
    int tid = threadIdx.x;
    int start = g_off[d];
    int deg = g_off[d + 1] - start;

    __shared__ float sden;
    __shared__ float svals[OUTC];
    if (tid == 0) sden = 0.f;
    __syncthreads();

    float add = g_ad2[d];
    float part = 0.f;
    for (int i = tid; i < deg; i += 64) {
        int s = g_src[start + i];
        float v = g_as2[s] + add;
        v = v > 0.f ? v : NEG * v;
        float ex = __expf(v);
        g_e2[start + i] = ex;
        part += ex;
    }
    atomicAdd(&sden, part);
    __syncthreads();

    if (tid < OUTC) {
        float acc = 0.f;
        for (int i = 0; i < deg; i++) {
            int s = g_src[start + i];
            acc += g_e2[start + i] * g_h2[(size_t)s * OUTC + tid];
        }
        svals[tid] = acc / (sden + 1e-16f) + b2[tid];
    }
    __syncthreads();
    if (tid < OUTC) {
        float m = -1e30f;
#pragma unroll 8
        for (int j = 0; j < OUTC; j++) m = fmaxf(m, svals[j]);
        float sum = 0.f;
#pragma unroll 8
        for (int j = 0; j < OUTC; j++) sum += __expf(svals[j] - m);
        out[(size_t)d * OUTC + tid] = svals[tid] - m - logf(sum);
    }
}

// ---------------- launch --------------------------------------------------------
extern "C" void kernel_launch(void* const* d_in, const int* in_sizes, int n_in,
                              void* d_out, int out_size) {
    const float* x   = (const float*)d_in[0];
    const int*   ei  = (const int*)d_in[1];
    const float* W1  = (const float*)d_in[2];
    const float* a1s = (const float*)d_in[3];
    const float* a1d = (const float*)d_in[4];
    const float* b1  = (const float*)d_in[5];
    const float* W2  = (const float*)d_in[6];
    const float* a2s = (const float*)d_in[7];
    const float* a2d = (const float*)d_in[8];
    const float* b2  = (const float*)d_in[9];
    float*       out = (float*)d_out;

    // CSR build
    zero_deg<<<(NN + 255) / 256, 256>>>();
    deg_hist<<<(ET + 255) / 256, 256>>>(ei);
    scan_kernel<<<1, 1024>>>();
    fill_csr<<<(ET + 255) / 256, 256>>>(ei);

    gemm1_kernel<<<dim3(2, (NN + 127) / 128), 256>>>(x, W1);
    alpha1_kernel<<<NN, 256>>>(a1s, a1d);

    gather1<<<NN, 256>>>(b1);

    gemm2_kernel<<<(NN + 127) / 128, 256>>>(W2, a2s, a2d);

    gather2<<<NN, 64>>>(b2, out);
}